// round 12
// baseline (speedup 1.0000x reference)
#include <cuda_runtime.h>
#include <cuda_bf16.h>

// QuantumFeatureExtractor — closed-form, float4 loads, STG.256 stores,
// block-level parameter precompute (uniform work hoisted out of threads).
//
//   m0 = cos(t4)cos(t0)cos(a0) + 0.5*sin(t4)cos(t2)*(cos(a0+a2) - cos(a0-a2))
//   m1 = cos(a1 + t1)
//   m2 = 0.5*cos(t0)*(cos(a0-a2) + cos(a0+a2))
//   m3 = cos(a1 + t1) * cos(t3) * cos(a3)
// (final Rz(t5) is a diagonal phase: no effect on probabilities)
//
// Thread k (262144 total): j4 = k&31, i = (k>>5)&63, b = k>>11.
// 2 lane-contiguous LDG.128 (issued before the param barrier, so DRAM
// latency overlaps the once-per-block param computation), 5 MUFU/patch,
// one st.global.v8.f32 (sm_103a 256-bit store) covering both patches.

__device__ __forceinline__ float4 qfe_patch(float a0, float a1, float a2, float a3,
                                            float A, float Bp, float Ch,
                                            float ct3, float t1) {
    const float c0 = __cosf(a0);
    const float cp = __cosf(a0 + a2);   // cos(a0+a2)
    const float cm = __cosf(a0 - a2);   // cos(a0-a2)
    const float m1 = __cosf(a1 + t1);
    const float c3 = __cosf(a3);
    const float m0 = fmaf(A, c0, Bp * (cp - cm));   // Bp = 0.5 sin t4 cos t2
    const float m2 = Ch * (cm + cp);                // Ch = 0.5 cos t0
    const float m3 = m1 * (ct3 * c3);
    return make_float4(m0, m1, m2, m3);
}

__global__ void __launch_bounds__(256) qfe_main(const float4* __restrict__ x4,
                                                const float* __restrict__ tp,
                                                float* __restrict__ out) {
    __shared__ float4 sp0;   // {A, Bp, Ch, ct3}
    __shared__ float  sp1;   // t1

    const int k  = blockIdx.x * 256 + threadIdx.x;   // 262144 threads
    const int j4 = k & 31;          // float4 column -> patches 2j4, 2j4+1
    const int i  = (k >> 5) & 63;   // patch row
    const int b  = k >> 11;         // batch

    const int in = b * 4096 + i * 64 + j4;
    // Data loads issued first: DRAM latency overlaps the param barrier.
    const float4 rA = x4[in];        // row 2i:   a0,a1 | a0',a1'
    const float4 rB = x4[in + 32];   // row 2i+1: a2,a3 | a2',a3'

    // Warp 0 computes the 5 derived uniform constants once per block.
    if (threadIdx.x < 32) {
        const float t0 = tp[0], t1 = tp[1], t2 = tp[2], t3 = tp[3], t4 = tp[4];
        float st4, ct4;
        __sincosf(t4, &st4, &ct4);
        const float ct0 = __cosf(t0);
        sp0 = make_float4(ct4 * ct0,                 // A
                          0.5f * (st4 * __cosf(t2)), // Bp
                          0.5f * ct0,                // Ch
                          __cosf(t3));               // ct3
        sp1 = t1;
    }
    __syncthreads();

    const float4 P  = sp0;    // one LDS.128 broadcast
    const float  t1 = sp1;    // one LDS.32 broadcast

    const float4 oa = qfe_patch(rA.x, rA.y, rB.x, rB.y, P.x, P.y, P.z, P.w, t1);
    const float4 ob = qfe_patch(rA.z, rA.w, rB.z, rB.w, P.x, P.y, P.z, P.w, t1);

    // Output float4 index of patch 2*j4 = in + j4 (even -> 32 B aligned).
    // Lane t covers bytes [32t, 32t+32) of the warp's contiguous 1024 B
    // span: one STG.256 per lane.
    float* dst = out + (size_t)(in + j4) * 4;
    asm volatile(
        "st.global.v8.f32 [%0], {%1, %2, %3, %4, %5, %6, %7, %8};"
        :: "l"(dst),
           "f"(oa.x), "f"(oa.y), "f"(oa.z), "f"(oa.w),
           "f"(ob.x), "f"(ob.y), "f"(ob.z), "f"(ob.w)
        : "memory");
}

extern "C" void kernel_launch(void* const* d_in, const int* in_sizes, int n_in,
                              void* d_out, int out_size) {
    const float* x  = (const float*)d_in[0];
    const float* tp = (const float*)d_in[1];
    if (n_in >= 2 && in_sizes[0] == 6) {   // defensive vs metadata ordering
        const float* s = x; x = tp; tp = s;
    }
    qfe_main<<<1024, 256>>>((const float4*)x, tp, (float*)d_out);
}

// round 13
// speedup vs baseline: 1.2692x; 1.2692x over previous
#include <cuda_runtime.h>
#include <cuda_bf16.h>

// QuantumFeatureExtractor — closed-form, float4 loads, single 256-bit store
// per thread (sm_103a st.global.v8.f32). Fully independent warps (no
// barriers, no smem): the R8 structure, with a finer launch granularity
// (2048 x 128) to cut the between-SM block-count imbalance (14-vs-13
// blocks/SM ~ 7% instead of 7-vs-6 ~ 17%).
//
//   m0 = cos(t4)cos(t0)cos(a0) + 0.5*sin(t4)cos(t2)*(cos(a0+a2) - cos(a0-a2))
//   m1 = cos(a1 + t1)
//   m2 = 0.5*cos(t0)*(cos(a0-a2) + cos(a0+a2))
//   m3 = cos(a1 + t1) * cos(t3) * cos(a3)
// (final Rz(t5) is a diagonal phase: no effect on probabilities)

__device__ __forceinline__ float4 qfe_patch(float a0, float a1, float a2, float a3,
                                            float A, float Bp, float Ch,
                                            float ct3, float t1) {
    const float c0 = __cosf(a0);
    const float cp = __cosf(a0 + a2);   // cos(a0+a2)
    const float cm = __cosf(a0 - a2);   // cos(a0-a2)
    const float m1 = __cosf(a1 + t1);
    const float c3 = __cosf(a3);
    const float m0 = fmaf(A, c0, Bp * (cp - cm));   // Bp = 0.5 sin t4 cos t2
    const float m2 = Ch * (cm + cp);                // Ch = 0.5 cos t0
    const float m3 = m1 * (ct3 * c3);
    return make_float4(m0, m1, m2, m3);
}

__global__ void __launch_bounds__(128) qfe_main(const float4* __restrict__ x4,
                                                const float* __restrict__ tp,
                                                float* __restrict__ out) {
    const int k  = blockIdx.x * 128 + threadIdx.x;   // 262144 threads
    const int j4 = k & 31;          // float4 column -> patches 2j4, 2j4+1
    const int i  = (k >> 5) & 63;   // patch row
    const int b  = k >> 11;         // batch

    const int in = b * 4096 + i * 64 + j4;
    // Both data loads issued back-to-back, lane-contiguous (512 B/warp each).
    const float4 rA = x4[in];        // row 2i:   a0,a1 | a0',a1'
    const float4 rB = x4[in + 32];   // row 2i+1: a2,a3 | a2',a3'

    // Uniform circuit params — per-warp, evaluated while loads are in flight.
    const float t0 = tp[0], t1 = tp[1], t2 = tp[2], t3 = tp[3], t4 = tp[4];
    float st4, ct4;
    __sincosf(t4, &st4, &ct4);
    const float ct0 = __cosf(t0);
    const float ct2 = __cosf(t2);
    const float ct3 = __cosf(t3);
    const float A  = ct4 * ct0;
    const float Bp = 0.5f * (st4 * ct2);
    const float Ch = 0.5f * ct0;

    const float4 oa = qfe_patch(rA.x, rA.y, rB.x, rB.y, A, Bp, Ch, ct3, t1);
    const float4 ob = qfe_patch(rA.z, rA.w, rB.z, rB.w, A, Bp, Ch, ct3, t1);

    // Output float4 index of patch 2*j4 = in + j4 (even -> 32 B aligned).
    // Lane t covers bytes [32t, 32t+32) of the warp's contiguous 1024 B
    // span: one STG.256 per lane.
    float* dst = out + (size_t)(in + j4) * 4;
    asm volatile(
        "st.global.v8.f32 [%0], {%1, %2, %3, %4, %5, %6, %7, %8};"
        :: "l"(dst),
           "f"(oa.x), "f"(oa.y), "f"(oa.z), "f"(oa.w),
           "f"(ob.x), "f"(ob.y), "f"(ob.z), "f"(ob.w)
        : "memory");
}

extern "C" void kernel_launch(void* const* d_in, const int* in_sizes, int n_in,
                              void* d_out, int out_size) {
    const float* x  = (const float*)d_in[0];
    const float* tp = (const float*)d_in[1];
    if (n_in >= 2 && in_sizes[0] == 6) {   // defensive vs metadata ordering
        const float* s = x; x = tp; tp = s;
    }
    qfe_main<<<2048, 128>>>((const float4*)x, tp, (float*)d_out);
}

// round 15
// speedup vs baseline: 1.2754x; 1.0048x over previous
#include <cuda_runtime.h>
#include <cuda_bf16.h>

// QuantumFeatureExtractor — closed-form, float4 loads, single 256-bit store
// per thread tagged L2::evict_first (output is write-once per replay and
// never re-read: don't let it evict the 8 MB input from GB300's 126 MB L2,
// so replay loads hit L2 instead of DRAM). Fully independent warps: no
// smem, no barriers. Otherwise identical to the best-measured structure
// (5.856 us at both 1024x256 and 2048x128).
//
//   m0 = cos(t4)cos(t0)cos(a0) + 0.5*sin(t4)cos(t2)*(cos(a0+a2) - cos(a0-a2))
//   m1 = cos(a1 + t1)
//   m2 = 0.5*cos(t0)*(cos(a0-a2) + cos(a0+a2))
//   m3 = cos(a1 + t1) * cos(t3) * cos(a3)
// (final Rz(t5) is a diagonal phase: no effect on probabilities)

__device__ __forceinline__ float4 qfe_patch(float a0, float a1, float a2, float a3,
                                            float A, float Bp, float Ch,
                                            float ct3, float t1) {
    const float c0 = __cosf(a0);
    const float cp = __cosf(a0 + a2);   // cos(a0+a2)
    const float cm = __cosf(a0 - a2);   // cos(a0-a2)
    const float m1 = __cosf(a1 + t1);
    const float c3 = __cosf(a3);
    const float m0 = fmaf(A, c0, Bp * (cp - cm));   // Bp = 0.5 sin t4 cos t2
    const float m2 = Ch * (cm + cp);                // Ch = 0.5 cos t0
    const float m3 = m1 * (ct3 * c3);
    return make_float4(m0, m1, m2, m3);
}

__global__ void __launch_bounds__(256) qfe_main(const float4* __restrict__ x4,
                                                const float* __restrict__ tp,
                                                float* __restrict__ out) {
    const int k  = blockIdx.x * 256 + threadIdx.x;   // 262144 threads
    const int j4 = k & 31;          // float4 column -> patches 2j4, 2j4+1
    const int i  = (k >> 5) & 63;   // patch row
    const int b  = k >> 11;         // batch

    const int in = b * 4096 + i * 64 + j4;
    // Both data loads issued back-to-back, lane-contiguous (512 B/warp each).
    const float4 rA = x4[in];        // row 2i:   a0,a1 | a0',a1'
    const float4 rB = x4[in + 32];   // row 2i+1: a2,a3 | a2',a3'

    // Uniform circuit params — per-warp, evaluated while loads are in flight.
    const float t0 = tp[0], t1 = tp[1], t2 = tp[2], t3 = tp[3], t4 = tp[4];
    float st4, ct4;
    __sincosf(t4, &st4, &ct4);
    const float ct0 = __cosf(t0);
    const float ct2 = __cosf(t2);
    const float ct3 = __cosf(t3);
    const float A  = ct4 * ct0;
    const float Bp = 0.5f * (st4 * ct2);
    const float Ch = 0.5f * ct0;

    const float4 oa = qfe_patch(rA.x, rA.y, rB.x, rB.y, A, Bp, Ch, ct3, t1);
    const float4 ob = qfe_patch(rA.z, rA.w, rB.z, rB.w, A, Bp, Ch, ct3, t1);

    // Output float4 index of patch 2*j4 = in + j4 (even -> 32 B aligned).
    // Lane t covers bytes [32t, 32t+32) of the warp's contiguous 1024 B
    // span: one STG.256 per lane, marked evict_first (write-once data).
    float* dst = out + (size_t)(in + j4) * 4;
    asm volatile(
        "st.global.L2::evict_first.v8.f32 [%0], {%1, %2, %3, %4, %5, %6, %7, %8};"
        :: "l"(dst),
           "f"(oa.x), "f"(oa.y), "f"(oa.z), "f"(oa.w),
           "f"(ob.x), "f"(ob.y), "f"(ob.z), "f"(ob.w)
        : "memory");
}

extern "C" void kernel_launch(void* const* d_in, const int* in_sizes, int n_in,
                              void* d_out, int out_size) {
    const float* x  = (const float*)d_in[0];
    const float* tp = (const float*)d_in[1];
    if (n_in >= 2 && in_sizes[0] == 6) {   // defensive vs metadata ordering
        const float* s = x; x = tp; tp = s;
    }
    qfe_main<<<1024, 256>>>((const float4*)x, tp, (float*)d_out);
}